// round 6
// baseline (speedup 1.0000x reference)
#include <cuda_runtime.h>
#include <math.h>
#include <float.h>

#define QLEN 1024
#define DMODEL 4096
#define NH 32
#define NKV 8
#define HD 128
#define OUTL 16
#define KEEP 256

// ---------------- scratch (static device globals; no allocation) ----------------
__device__ float g_qlin[QLEN * DMODEL];
__device__ float g_klin[QLEN * NKV * HD];
__device__ float g_vlin[QLEN * NKV * HD];
__device__ float g_qr[NH * QLEN * HD];
__device__ float g_kr[NKV * QLEN * HD];
__device__ float g_vr[NKV * QLEN * HD];
__device__ float g_gq[NH * QLEN * OUTL];
__device__ float g_gk[NH * QLEN * OUTL];
__device__ float g_o[QLEN * NH * HD];

// ---------------- near-exact fp32 GEMM: C[M,N] = A[M,K] @ B[K,N] ----------------
// 128-length sequential FMA partials folded into a Neumaier-compensated master.
// Accumulation error ~11 ulp-units (vs ~64u for a plain 4096 sequential chain),
// i.e. below any plausible reference reduction's own error -> divergence vs the
// fp32 reference is minimized regardless of the order the reference used.
#define BM 128
#define BN 64
#define BK 16

__global__ __launch_bounds__(256) void gemm_acc(
    const float* __restrict__ A, const float* __restrict__ B, float* __restrict__ C,
    int M, int N, int K)
{
    __shared__ float As[BK][BM];
    __shared__ float Bs[BK][BN];

    int tid = threadIdx.x;
    int bm = blockIdx.y * BM;
    int bn = blockIdx.x * BN;

    int trow = (tid >> 4) * 8;   // 0..120
    int tcol = (tid & 15) * 4;   // 0..60

    float mst[8][4], cmp[8][4], prt[8][4];
#pragma unroll
    for (int i = 0; i < 8; ++i)
#pragma unroll
        for (int j = 0; j < 4; ++j) { mst[i][j] = 0.f; cmp[i][j] = 0.f; prt[i][j] = 0.f; }

    int ntiles = K / BK;
    for (int t = 0; t < ntiles; ++t) {
        int k0 = t * BK;
        // A tile: 128x16 = 512 float4, 2 per thread
#pragma unroll
        for (int i = 0; i < 2; ++i) {
            int idx = tid + i * 256;
            int ar = idx >> 2;
            int ac = (idx & 3) << 2;
            float4 av = *(const float4*)&A[(size_t)(bm + ar) * K + k0 + ac];
            As[ac + 0][ar] = av.x;
            As[ac + 1][ar] = av.y;
            As[ac + 2][ar] = av.z;
            As[ac + 3][ar] = av.w;
        }
        // B tile: 16x64 = 256 float4, 1 per thread
        {
            int br = tid >> 4;
            int bc = (tid & 15) << 2;
            float4 bv = *(const float4*)&B[(size_t)(k0 + br) * N + bn + bc];
            *(float4*)&Bs[br][bc] = bv;
        }
        __syncthreads();

#pragma unroll
        for (int k = 0; k < BK; ++k) {
            float ra[8], rb[4];
            float4 a0 = *(float4*)&As[k][trow];
            float4 a1 = *(float4*)&As[k][trow + 4];
            ra[0] = a0.x; ra[1] = a0.y; ra[2] = a0.z; ra[3] = a0.w;
            ra[4] = a1.x; ra[5] = a1.y; ra[6] = a1.z; ra[7] = a1.w;
            float4 b0 = *(float4*)&Bs[k][tcol];
            rb[0] = b0.x; rb[1] = b0.y; rb[2] = b0.z; rb[3] = b0.w;
#pragma unroll
            for (int i = 0; i < 8; ++i)
#pragma unroll
                for (int j = 0; j < 4; ++j)
                    prt[i][j] = __fmaf_rn(ra[i], rb[j], prt[i][j]);
        }
        __syncthreads();

        // fold partial into compensated master every 8 tiles (128 k)
        if ((t & 7) == 7) {
#pragma unroll
            for (int i = 0; i < 8; ++i)
#pragma unroll
                for (int j = 0; j < 4; ++j) {
                    float m = mst[i][j], p = prt[i][j];
                    float s = __fadd_rn(m, p);
                    float e1 = __fadd_rn(__fadd_rn(m, -s), p);
                    float e2 = __fadd_rn(__fadd_rn(p, -s), m);
                    float e = (fabsf(m) >= fabsf(p)) ? e1 : e2;
                    cmp[i][j] = __fadd_rn(cmp[i][j], e);
                    mst[i][j] = s;
                    prt[i][j] = 0.f;
                }
        }
    }

#pragma unroll
    for (int i = 0; i < 8; ++i) {
        float4 o;
        o.x = __fadd_rn(mst[i][0], cmp[i][0]);
        o.y = __fadd_rn(mst[i][1], cmp[i][1]);
        o.z = __fadd_rn(mst[i][2], cmp[i][2]);
        o.w = __fadd_rn(mst[i][3], cmp[i][3]);
        *(float4*)&C[(size_t)(bm + trow + i) * N + bn + tcol] = o;
    }
}

// ---------------- RoPE + layout transpose (precision-matched) ----------------
__global__ void rope_kernel()
{
    int p = blockIdx.x;
    int hh = blockIdx.y;
    int d = threadIdx.x;

    int i = d & 63;
    float P = (float)pow(10000.0, (double)(2 * i) / 128.0);   // correctly rounded fp32 pow
    float invf = __fdiv_rn(1.0f, P);                           // 1.0 / P, as in reference
    float ang = __fmul_rn((float)p, invf);
    float c = (float)cos((double)ang);
    float s = (float)sin((double)ang);

    if (hh < NH) {
        const float* base = &g_qlin[(size_t)p * DMODEL + hh * HD];
        float v = base[d];
        float other = (d < 64) ? -base[d + 64] : base[d - 64];
        g_qr[((size_t)hh * QLEN + p) * HD + d] =
            __fadd_rn(__fmul_rn(v, c), __fmul_rn(other, s));
    } else if (hh < NH + NKV) {
        int kvh = hh - NH;
        const float* base = &g_klin[(size_t)p * (NKV * HD) + kvh * HD];
        float v = base[d];
        float other = (d < 64) ? -base[d + 64] : base[d - 64];
        g_kr[((size_t)kvh * QLEN + p) * HD + d] =
            __fadd_rn(__fmul_rn(v, c), __fmul_rn(other, s));
    } else {
        int kvh = hh - NH - NKV;
        g_vr[((size_t)kvh * QLEN + p) * HD + d] =
            g_vlin[(size_t)p * (NKV * HD) + kvh * HD + d];
    }
}

// ---------------- label build: channel gather + 4-bit pseudo-quantize ------------
__global__ void gqk_kernel(const int* __restrict__ sorted_channel)
{
    int p = blockIdx.x;
    int h = blockIdx.y;
    int lane = threadIdx.x;      // 32 threads: 0-15 -> gq, 16-31 -> gk
    int j = lane & 15;
    bool isK = lane >= 16;

    int ch = sorted_channel[h * HD + j];
    float t;
    if (!isK) t = g_qr[((size_t)h * QLEN + p) * HD + ch];
    else      t = g_kr[((size_t)(h >> 2) * QLEN + p) * HD + ch];

    float mn = t, mx = t;
#pragma unroll
    for (int off = 1; off < 16; off <<= 1) {
        mn = fminf(mn, __shfl_xor_sync(0xffffffffu, mn, off));
        mx = fmaxf(mx, __shfl_xor_sync(0xffffffffu, mx, off));
    }
    float rng = __fadd_rn(mx, -mn);
    if (rng == 0.0f) rng = 1.0f;
    float scale = __fdiv_rn(15.0f, rng);
    float qv = rintf(__fmul_rn(__fadd_rn(t, -mn), scale));
    qv = fminf(fmaxf(qv, 0.0f), 15.0f);
    float outv = __fadd_rn(__fdiv_rn(qv, scale), mn);

    if (!isK) g_gq[((size_t)h * QLEN + p) * OUTL + j] = outv;
    else      g_gk[((size_t)h * QLEN + p) * OUTL + j] = outv;
}

// ---------------- fused gattn -> stable top-256 -> attn -> softmax -> AV ----
__global__ __launch_bounds__(256) void attn_kernel()
{
    int p = blockIdx.x;
    int h = blockIdx.y;
    int kvh = h >> 2;
    int tid = threadIdx.x;
    int lane = tid & 31;
    int warp = tid >> 5;

    __shared__ float gq_s[OUTL];
    __shared__ float q_s[HD];
    __shared__ unsigned keys[QLEN];
    __shared__ unsigned hist[256];
    __shared__ unsigned suf[256];
    __shared__ int kept_raw[KEEP];
    __shared__ int kept_idx[KEEP];
    __shared__ float attw[KEEP];
    __shared__ int kcount;
    __shared__ unsigned sh_prefix;
    __shared__ int sh_want;
    __shared__ int wcnt[8];
    __shared__ int eqbase;
    __shared__ float red[8];
    __shared__ float sh_scalar;

    if (tid < OUTL) gq_s[tid] = g_gq[((size_t)h * QLEN + p) * OUTL + tid];
    if (tid < HD)   q_s[tid] = g_qr[((size_t)h * QLEN + p) * HD + tid];
    if (tid == 0) { kcount = 0; eqbase = 0; }
    __syncthreads();

    int nvalid = p + 1;

    // 1. gattn keys: strict ascending sequential FMA chain, exact /4.
    //    Canonicalize -0.0 -> +0.0 (reference stable sort treats them equal).
    for (int j = tid; j < nvalid; j += 256) {
        const float* g = &g_gk[((size_t)h * QLEN + j) * OUTL];
        float s = __fmul_rn(g[0], gq_s[0]);
#pragma unroll
        for (int d = 1; d < OUTL; ++d)
            s = __fmaf_rn(g[d], gq_s[d], s);
        s = __fmul_rn(s, 0.25f);
        unsigned u = __float_as_uint(s);
        if ((u << 1) == 0u) u = 0u;          // -0.0 == +0.0 in the sort order
        u ^= (u & 0x80000000u) ? 0xFFFFFFFFu : 0x80000000u;
        keys[j] = u;
    }
    __syncthreads();

    // 2. stable top-KEEP selection
    int cnt;
    if (nvalid <= KEEP) {
        for (int j = tid; j < nvalid; j += 256) kept_idx[j] = j;
        cnt = nvalid;
        __syncthreads();
    } else {
        unsigned prefix = 0;
        int want = KEEP;
        for (int byte = 3; byte >= 0; --byte) {
            hist[tid] = 0;
            __syncthreads();
            int shift = byte * 8;
            unsigned pmask = (byte == 3) ? 0u : (0xFFFFFFFFu << (shift + 8));
            for (int j = tid; j < nvalid; j += 256) {
                unsigned u = keys[j];
                if ((u & pmask) == prefix)
                    atomicAdd(&hist[(u >> shift) & 255u], 1u);
            }
            __syncthreads();
            suf[tid] = hist[tid];
            __syncthreads();
            for (int off = 1; off < 256; off <<= 1) {
                unsigned v = (tid + off < 256) ? suf[tid + off] : 0u;
                __syncthreads();
                suf[tid] += v;
                __syncthreads();
            }
            unsigned above = suf[tid] - hist[tid];
            if (suf[tid] >= (unsigned)want && above < (unsigned)want) {
                sh_prefix = prefix | ((unsigned)tid << shift);
                sh_want = want - (int)above;
            }
            __syncthreads();
            prefix = sh_prefix;
            want = sh_want;
            __syncthreads();
        }
        unsigned uT = prefix;
        int r = want;

        for (int chunk = 0; chunk < QLEN / 256; ++chunk) {
            int j = chunk * 256 + tid;
            bool isval = j < nvalid;
            unsigned u = isval ? keys[j] : 0u;
            bool gt = isval && (u > uT);
            bool eq = isval && (u == uT);
            if (gt) { int s = atomicAdd(&kcount, 1); kept_raw[s] = j; }
            unsigned bal = __ballot_sync(0xffffffffu, eq);
            if (lane == 0) wcnt[warp] = __popc(bal);
            __syncthreads();
            int woff = 0;
            for (int w = 0; w < warp; ++w) woff += wcnt[w];
            int eqidx = eqbase + woff + __popc(bal & ((1u << lane) - 1u));
            if (eq && eqidx < r) { int s = atomicAdd(&kcount, 1); kept_raw[s] = j; }
            __syncthreads();
            if (tid == 0) {
                int tot = 0;
                for (int w = 0; w < 8; ++w) tot += wcnt[w];
                eqbase += tot;
            }
            __syncthreads();
        }
        cnt = kcount;
        __syncthreads();

        // sort kept indices ascending (rank by count of smaller elements)
        if (tid < cnt) {
            int mine = kept_raw[tid];
            int rk = 0;
            for (int s = 0; s < cnt; ++s) rk += (kept_raw[s] < mine);
            kept_idx[rk] = mine;
        }
        __syncthreads();
    }
    __syncthreads();

    // 3. attn scores on kept columns (warp per column)
    for (int c = warp; c < cnt; c += 8) {
        int j = kept_idx[c];
        const float* kvp = &g_kr[((size_t)kvh * QLEN + j) * HD];
        float s = 0.f;
#pragma unroll
        for (int d = lane; d < HD; d += 32) s = __fmaf_rn(q_s[d], kvp[d], s);
#pragma unroll
        for (int off = 16; off; off >>= 1) s += __shfl_xor_sync(0xffffffffu, s, off);
        if (lane == 0) attw[c] = s / 11.313708498984761f;   // /sqrt(128)
    }
    __syncthreads();

    // 4. softmax over kept (exp in double -> correctly rounded fp32 exp)
    float vmax = -FLT_MAX;
    for (int c = tid; c < cnt; c += 256) vmax = fmaxf(vmax, attw[c]);
#pragma unroll
    for (int off = 16; off; off >>= 1)
        vmax = fmaxf(vmax, __shfl_xor_sync(0xffffffffu, vmax, off));
    if (lane == 0) red[warp] = vmax;
    __syncthreads();
    if (warp == 0) {
        float m = (lane < 8) ? red[lane] : -FLT_MAX;
#pragma unroll
        for (int off = 4; off; off >>= 1)
            m = fmaxf(m, __shfl_xor_sync(0xffffffffu, m, off));
        if (lane == 0) sh_scalar = m;
    }
    __syncthreads();
    float M = sh_scalar;

    float lsum = 0.f;
    for (int c = tid; c < cnt; c += 256) {
        float e = (float)exp((double)__fadd_rn(attw[c], -M));
        attw[c] = e;
        lsum += e;
    }
#pragma unroll
    for (int off = 16; off; off >>= 1)
        lsum += __shfl_xor_sync(0xffffffffu, lsum, off);
    if (lane == 0) red[warp] = lsum;
    __syncthreads();
    if (warp == 0) {
        float s2 = (lane < 8) ? red[lane] : 0.f;
#pragma unroll
        for (int off = 4; off; off >>= 1)
            s2 += __shfl_xor_sync(0xffffffffu, s2, off);
        if (lane == 0) sh_scalar = s2;
    }
    __syncthreads();
    float denom = sh_scalar;

    // normalize weights by DIVISION (jax.nn.softmax divides)
    for (int c = tid; c < cnt; c += 256)
        attw[c] = __fdiv_rn(attw[c], denom);
    __syncthreads();

    // 5. AV: strict sequential ascending-k FMA chain per output dim
    if (tid < HD) {
        float acc = 0.f;
        const float* vbase = &g_vr[(size_t)kvh * QLEN * HD + tid];
        for (int c = 0; c < cnt; ++c)
            acc = __fmaf_rn(attw[c], __ldg(&vbase[(size_t)kept_idx[c] * HD]), acc);
        g_o[(size_t)p * (NH * HD) + h * HD + tid] = acc;
    }
}

// ---------------- launch ----------------
extern "C" void kernel_launch(void* const* d_in, const int* in_sizes, int n_in,
                              void* d_out, int out_size)
{
    const float* hidden = (const float*)d_in[0];
    const float* Wq = (const float*)d_in[3];
    const float* Wk = (const float*)d_in[4];
    const float* Wv = (const float*)d_in[5];
    const float* Wo = (const float*)d_in[6];
    const int* sorted_channel = (const int*)d_in[7];
    float* out = (float*)d_out;

    float *qlin, *klin, *vlin, *o;
    cudaGetSymbolAddress((void**)&qlin, g_qlin);
    cudaGetSymbolAddress((void**)&klin, g_klin);
    cudaGetSymbolAddress((void**)&vlin, g_vlin);
    cudaGetSymbolAddress((void**)&o, g_o);

    dim3 t256(256);
    gemm_acc<<<dim3(DMODEL / BN, QLEN / BM), t256>>>(hidden, Wq, qlin, QLEN, DMODEL, DMODEL);
    gemm_acc<<<dim3((NKV * HD) / BN, QLEN / BM), t256>>>(hidden, Wk, klin, QLEN, NKV * HD, DMODEL);
    gemm_acc<<<dim3((NKV * HD) / BN, QLEN / BM), t256>>>(hidden, Wv, vlin, QLEN, NKV * HD, DMODEL);
    rope_kernel<<<dim3(QLEN, NH + 2 * NKV), 128>>>();
    gqk_kernel<<<dim3(QLEN, NH), 32>>>(sorted_channel);
    attn_kernel<<<dim3(QLEN, NH), 256>>>();
    gemm_acc<<<dim3(DMODEL / BN, QLEN / BM), t256>>>(o, Wo, out, QLEN, DMODEL, DMODEL);
}

// round 7
// speedup vs baseline: 1.1463x; 1.1463x over previous
#include <cuda_runtime.h>
#include <math.h>
#include <float.h>

#define QLEN 1024
#define DMODEL 4096
#define NH 32
#define NKV 8
#define HD 128
#define OUTL 16
#define KEEP 256

// ---------------- scratch (static device globals; no allocation) ----------------
__device__ float g_qlin[QLEN * DMODEL];
__device__ float g_klin[QLEN * NKV * HD];
__device__ float g_vlin[QLEN * NKV * HD];
__device__ float g_qr[NH * QLEN * HD];
__device__ float g_kr[NKV * QLEN * HD];
__device__ float g_vr[NKV * QLEN * HD];
__device__ float g_gq[NH * QLEN * OUTL];
__device__ float g_gk[NH * QLEN * OUTL];
__device__ float g_o[QLEN * NH * HD];

// ---------------- 3xTF32 tensor-core GEMM with two-level fp32 accumulation ------
// C[M,N] = A[M,K] @ B[K,N].  Each fp32 operand split x = hi + lo (tf32 pair);
// product = hi*hi + lo*hi + hi*lo via mma.sync.m16n8k8 (error ~2^-22 per product).
// MMA accumulates k=128 chunks in fp32; chunk partials folded into fp32 master
// (32 folds for K=4096) -> total accumulation error ~6 ulp-units, at or below the
// compensated SIMT scheme that produced rel_err 1.08e-4.
#define GBM 128
#define GBN 64
#define GBK 32
#define SPITCH (GBK + 4)

__device__ __forceinline__ void tf32_split(float x, unsigned& hi, unsigned& lo) {
    unsigned h;
    asm("cvt.rna.tf32.f32 %0, %1;" : "=r"(h) : "f"(x));
    float r = __fadd_rn(x, -__uint_as_float(h));
    unsigned l;
    asm("cvt.rna.tf32.f32 %0, %1;" : "=r"(l) : "f"(r));
    hi = h; lo = l;
}

__device__ __forceinline__ void mma_tf32(float* d, const unsigned* a, const unsigned* b) {
    asm volatile(
        "mma.sync.aligned.m16n8k8.row.col.f32.tf32.tf32.f32 "
        "{%0,%1,%2,%3}, {%4,%5,%6,%7}, {%8,%9}, {%0,%1,%2,%3};"
        : "+f"(d[0]), "+f"(d[1]), "+f"(d[2]), "+f"(d[3])
        : "r"(a[0]), "r"(a[1]), "r"(a[2]), "r"(a[3]), "r"(b[0]), "r"(b[1]));
}

__global__ __launch_bounds__(256) void gemm_tf32(
    const float* __restrict__ A,
    const float* __restrict__ B0, float* __restrict__ C0,
    const float* __restrict__ B1, float* __restrict__ C1,
    int N, int K)
{
    const float* B = (blockIdx.z == 0) ? B0 : B1;
    float* C = (blockIdx.z == 0) ? C0 : C1;

    __shared__ float As[GBM][SPITCH];      // [m][k], pitch 36 -> conflict-free frag reads
    __shared__ float Bs[GBN][SPITCH];      // transposed [n][k], pitch 36

    int tid = threadIdx.x;
    int lane = tid & 31;
    int wid = tid >> 5;
    int wm = (wid >> 1) * 32;              // warp m offset: 0,32,64,96
    int wn = (wid & 1) * 32;               // warp n offset: 0,32
    int g = lane >> 2;                     // 0..7
    int t4 = lane & 3;                     // 0..3

    int bm = blockIdx.y * GBM;
    int bn = blockIdx.x * GBN;

    float acc[2][4][4];                    // chunk accumulator (MMA target)
    float mst[2][4][4];                    // master
#pragma unroll
    for (int mt = 0; mt < 2; ++mt)
#pragma unroll
        for (int nt = 0; nt < 4; ++nt)
#pragma unroll
            for (int r = 0; r < 4; ++r) { acc[mt][nt][r] = 0.f; mst[mt][nt][r] = 0.f; }

    int ntiles = K / GBK;
    for (int t = 0; t < ntiles; ++t) {
        int k0 = t * GBK;
        // A tile: 128x32 floats = 1024 float4, 4 per thread
#pragma unroll
        for (int i = 0; i < 4; ++i) {
            int idx = tid + i * 256;
            int r = idx >> 3;
            int c = (idx & 7) << 2;
            float4 v = *(const float4*)&A[(size_t)(bm + r) * K + k0 + c];
            *(float4*)&As[r][c] = v;
        }
        // B tile: 32x64 floats = 512 float4, 2 per thread, store transposed
#pragma unroll
        for (int i = 0; i < 2; ++i) {
            int idx = tid + i * 256;
            int k = idx >> 4;
            int n4 = (idx & 15) << 2;
            float4 v = *(const float4*)&B[(size_t)(k0 + k) * N + bn + n4];
            Bs[n4 + 0][k] = v.x;
            Bs[n4 + 1][k] = v.y;
            Bs[n4 + 2][k] = v.z;
            Bs[n4 + 3][k] = v.w;
        }
        __syncthreads();

#pragma unroll
        for (int ks = 0; ks < GBK / 8; ++ks) {
            int kb = ks * 8;
            unsigned ah[2][4], al[2][4];
#pragma unroll
            for (int mt = 0; mt < 2; ++mt) {
                int r0 = wm + mt * 16;
                tf32_split(As[r0 + g][kb + t4],          ah[mt][0], al[mt][0]);
                tf32_split(As[r0 + g + 8][kb + t4],      ah[mt][1], al[mt][1]);
                tf32_split(As[r0 + g][kb + t4 + 4],      ah[mt][2], al[mt][2]);
                tf32_split(As[r0 + g + 8][kb + t4 + 4],  ah[mt][3], al[mt][3]);
            }
            unsigned bh[4][2], bl[4][2];
#pragma unroll
            for (int nt = 0; nt < 4; ++nt) {
                int col = wn + nt * 8 + g;
                tf32_split(Bs[col][kb + t4],     bh[nt][0], bl[nt][0]);
                tf32_split(Bs[col][kb + t4 + 4], bh[nt][1], bl[nt][1]);
            }
#pragma unroll
            for (int mt = 0; mt < 2; ++mt)
#pragma unroll
                for (int nt = 0; nt < 4; ++nt) {
                    mma_tf32(acc[mt][nt], ah[mt], bh[nt]);
                    mma_tf32(acc[mt][nt], al[mt], bh[nt]);
                    mma_tf32(acc[mt][nt], ah[mt], bl[nt]);
                }
        }
        __syncthreads();

        // fold chunk (k=128) into master
        if ((t & 3) == 3) {
#pragma unroll
            for (int mt = 0; mt < 2; ++mt)
#pragma unroll
                for (int nt = 0; nt < 4; ++nt)
#pragma unroll
                    for (int r = 0; r < 4; ++r) {
                        mst[mt][nt][r] = __fadd_rn(mst[mt][nt][r], acc[mt][nt][r]);
                        acc[mt][nt][r] = 0.f;
                    }
        }
    }

#pragma unroll
    for (int mt = 0; mt < 2; ++mt)
#pragma unroll
        for (int nt = 0; nt < 4; ++nt) {
            int r0 = bm + wm + mt * 16 + g;
            int c0 = bn + wn + nt * 8 + t4 * 2;
            *(float2*)&C[(size_t)r0 * N + c0] =
                make_float2(mst[mt][nt][0], mst[mt][nt][1]);
            *(float2*)&C[(size_t)(r0 + 8) * N + c0] =
                make_float2(mst[mt][nt][2], mst[mt][nt][3]);
        }
}

// ---------------- RoPE + layout transpose (precision-matched) ----------------
__global__ void rope_kernel()
{
    int p = blockIdx.x;
    int hh = blockIdx.y;
    int d = threadIdx.x;

    int i = d & 63;
    float P = (float)pow(10000.0, (double)(2 * i) / 128.0);
    float invf = __fdiv_rn(1.0f, P);
    float ang = __fmul_rn((float)p, invf);
    float c = (float)cos((double)ang);
    float s = (float)sin((double)ang);

    if (hh < NH) {
        const float* base = &g_qlin[(size_t)p * DMODEL + hh * HD];
        float v = base[d];
        float other = (d < 64) ? -base[d + 64] : base[d - 64];
        g_qr[((size_t)hh * QLEN + p) * HD + d] =
            __fadd_rn(__fmul_rn(v, c), __fmul_rn(other, s));
    } else if (hh < NH + NKV) {
        int kvh = hh - NH;
        const float* base = &g_klin[(size_t)p * (NKV * HD) + kvh * HD];
        float v = base[d];
        float other = (d < 64) ? -base[d + 64] : base[d - 64];
        g_kr[((size_t)kvh * QLEN + p) * HD + d] =
            __fadd_rn(__fmul_rn(v, c), __fmul_rn(other, s));
    } else {
        int kvh = hh - NH - NKV;
        g_vr[((size_t)kvh * QLEN + p) * HD + d] =
            g_vlin[(size_t)p * (NKV * HD) + kvh * HD + d];
    }
}

// ---------------- label build: channel gather + 4-bit pseudo-quantize ------------
__global__ void gqk_kernel(const int* __restrict__ sorted_channel)
{
    int p = blockIdx.x;
    int h = blockIdx.y;
    int lane = threadIdx.x;
    int j = lane & 15;
    bool isK = lane >= 16;

    int ch = sorted_channel[h * HD + j];
    float t;
    if (!isK) t = g_qr[((size_t)h * QLEN + p) * HD + ch];
    else      t = g_kr[((size_t)(h >> 2) * QLEN + p) * HD + ch];

    float mn = t, mx = t;
#pragma unroll
    for (int off = 1; off < 16; off <<= 1) {
        mn = fminf(mn, __shfl_xor_sync(0xffffffffu, mn, off));
        mx = fmaxf(mx, __shfl_xor_sync(0xffffffffu, mx, off));
    }
    float rng = __fadd_rn(mx, -mn);
    if (rng == 0.0f) rng = 1.0f;
    float scale = __fdiv_rn(15.0f, rng);
    float qv = rintf(__fmul_rn(__fadd_rn(t, -mn), scale));
    qv = fminf(fmaxf(qv, 0.0f), 15.0f);
    float outv = __fadd_rn(__fdiv_rn(qv, scale), mn);

    if (!isK) g_gq[((size_t)h * QLEN + p) * OUTL + j] = outv;
    else      g_gk[((size_t)h * QLEN + p) * OUTL + j] = outv;
}

// ---------------- fused gattn -> stable top-256 -> attn -> softmax -> AV ----
__global__ __launch_bounds__(256) void attn_kernel()
{
    int p = blockIdx.x;
    int h = blockIdx.y;
    int kvh = h >> 2;
    int tid = threadIdx.x;
    int lane = tid & 31;
    int warp = tid >> 5;

    __shared__ float gq_s[OUTL];
    __shared__ float q_s[HD];
    __shared__ unsigned keys[QLEN];
    __shared__ unsigned hist[256];
    __shared__ unsigned suf[256];
    __shared__ int kept_raw[KEEP];
    __shared__ int kept_idx[KEEP];
    __shared__ float attw[KEEP];
    __shared__ int kcount;
    __shared__ unsigned sh_prefix;
    __shared__ int sh_want;
    __shared__ int wcnt[8];
    __shared__ int eqbase;
    __shared__ float red[8];
    __shared__ float sh_scalar;

    if (tid < OUTL) gq_s[tid] = g_gq[((size_t)h * QLEN + p) * OUTL + tid];
    if (tid < HD)   q_s[tid] = g_qr[((size_t)h * QLEN + p) * HD + tid];
    if (tid == 0) { kcount = 0; eqbase = 0; }
    __syncthreads();

    int nvalid = p + 1;

    // 1. gattn keys: strict ascending sequential FMA chain, exact /4.
    for (int j = tid; j < nvalid; j += 256) {
        const float* g = &g_gk[((size_t)h * QLEN + j) * OUTL];
        float s = __fmul_rn(g[0], gq_s[0]);
#pragma unroll
        for (int d = 1; d < OUTL; ++d)
            s = __fmaf_rn(g[d], gq_s[d], s);
        s = __fmul_rn(s, 0.25f);
        unsigned u = __float_as_uint(s);
        if ((u << 1) == 0u) u = 0u;          // -0.0 == +0.0
        u ^= (u & 0x80000000u) ? 0xFFFFFFFFu : 0x80000000u;
        keys[j] = u;
    }
    __syncthreads();

    // 2. stable top-KEEP selection
    int cnt;
    if (nvalid <= KEEP) {
        for (int j = tid; j < nvalid; j += 256) kept_idx[j] = j;
        cnt = nvalid;
        __syncthreads();
    } else {
        unsigned prefix = 0;
        int want = KEEP;
        for (int byte = 3; byte >= 0; --byte) {
            hist[tid] = 0;
            __syncthreads();
            int shift = byte * 8;
            unsigned pmask = (byte == 3) ? 0u : (0xFFFFFFFFu << (shift + 8));
            for (int j = tid; j < nvalid; j += 256) {
                unsigned u = keys[j];
                if ((u & pmask) == prefix)
                    atomicAdd(&hist[(u >> shift) & 255u], 1u);
            }
            __syncthreads();
            suf[tid] = hist[tid];
            __syncthreads();
            for (int off = 1; off < 256; off <<= 1) {
                unsigned v = (tid + off < 256) ? suf[tid + off] : 0u;
                __syncthreads();
                suf[tid] += v;
                __syncthreads();
            }
            unsigned above = suf[tid] - hist[tid];
            if (suf[tid] >= (unsigned)want && above < (unsigned)want) {
                sh_prefix = prefix | ((unsigned)tid << shift);
                sh_want = want - (int)above;
            }
            __syncthreads();
            prefix = sh_prefix;
            want = sh_want;
            __syncthreads();
        }
        unsigned uT = prefix;
        int r = want;

        for (int chunk = 0; chunk < QLEN / 256; ++chunk) {
            int j = chunk * 256 + tid;
            bool isval = j < nvalid;
            unsigned u = isval ? keys[j] : 0u;
            bool gt = isval && (u > uT);
            bool eq = isval && (u == uT);
            if (gt) { int s = atomicAdd(&kcount, 1); kept_raw[s] = j; }
            unsigned bal = __ballot_sync(0xffffffffu, eq);
            if (lane == 0) wcnt[warp] = __popc(bal);
            __syncthreads();
            int woff = 0;
            for (int w = 0; w < warp; ++w) woff += wcnt[w];
            int eqidx = eqbase + woff + __popc(bal & ((1u << lane) - 1u));
            if (eq && eqidx < r) { int s = atomicAdd(&kcount, 1); kept_raw[s] = j; }
            __syncthreads();
            if (tid == 0) {
                int tot = 0;
                for (int w = 0; w < 8; ++w) tot += wcnt[w];
                eqbase += tot;
            }
            __syncthreads();
        }
        cnt = kcount;
        __syncthreads();

        if (tid < cnt) {
            int mine = kept_raw[tid];
            int rk = 0;
            for (int s = 0; s < cnt; ++s) rk += (kept_raw[s] < mine);
            kept_idx[rk] = mine;
        }
        __syncthreads();
    }
    __syncthreads();

    // 3. attn scores on kept columns (warp per column)
    for (int c = warp; c < cnt; c += 8) {
        int j = kept_idx[c];
        const float* kvp = &g_kr[((size_t)kvh * QLEN + j) * HD];
        float s = 0.f;
#pragma unroll
        for (int d = lane; d < HD; d += 32) s = __fmaf_rn(q_s[d], kvp[d], s);
#pragma unroll
        for (int off = 16; off; off >>= 1) s += __shfl_xor_sync(0xffffffffu, s, off);
        if (lane == 0) attw[c] = s / 11.313708498984761f;
    }
    __syncthreads();

    // 4. softmax over kept (exp via double -> correctly rounded fp32)
    float vmax = -FLT_MAX;
    for (int c = tid; c < cnt; c += 256) vmax = fmaxf(vmax, attw[c]);
#pragma unroll
    for (int off = 16; off; off >>= 1)
        vmax = fmaxf(vmax, __shfl_xor_sync(0xffffffffu, vmax, off));
    if (lane == 0) red[warp] = vmax;
    __syncthreads();
    if (warp == 0) {
        float m = (lane < 8) ? red[lane] : -FLT_MAX;
#pragma unroll
        for (int off = 4; off; off >>= 1)
            m = fmaxf(m, __shfl_xor_sync(0xffffffffu, m, off));
        if (lane == 0) sh_scalar = m;
    }
    __syncthreads();
    float M = sh_scalar;

    float lsum = 0.f;
    for (int c = tid; c < cnt; c += 256) {
        float e = (float)exp((double)__fadd_rn(attw[c], -M));
        attw[c] = e;
        lsum += e;
    }
#pragma unroll
    for (int off = 16; off; off >>= 1)
        lsum += __shfl_xor_sync(0xffffffffu, lsum, off);
    if (lane == 0) red[warp] = lsum;
    __syncthreads();
    if (warp == 0) {
        float s2 = (lane < 8) ? red[lane] : 0.f;
#pragma unroll
        for (int off = 4; off; off >>= 1)
            s2 += __shfl_xor_sync(0xffffffffu, s2, off);
        if (lane == 0) sh_scalar = s2;
    }
    __syncthreads();
    float denom = sh_scalar;

    for (int c = tid; c < cnt; c += 256)
        attw[c] = __fdiv_rn(attw[c], denom);
    __syncthreads();

    // 5. AV: strict sequential ascending-k FMA chain per output dim
    if (tid < HD) {
        float acc = 0.f;
        const float* vbase = &g_vr[(size_t)kvh * QLEN * HD + tid];
        for (int c = 0; c < cnt; ++c)
            acc = __fmaf_rn(attw[c], __ldg(&vbase[(size_t)kept_idx[c] * HD]), acc);
        g_o[(size_t)p * (NH * HD) + h * HD + tid] = acc;
    }
}

// ---------------- launch ----------------
extern "C" void kernel_launch(void* const* d_in, const int* in_sizes, int n_in,
                              void* d_out, int out_size)
{
    const float* hidden = (const float*)d_in[0];
    const float* Wq = (const float*)d_in[3];
    const float* Wk = (const float*)d_in[4];
    const float* Wv = (const float*)d_in[5];
    const float* Wo = (const float*)d_in[6];
    const int* sorted_channel = (const int*)d_in[7];
    float* out = (float*)d_out;

    float *qlin, *klin, *vlin, *o;
    cudaGetSymbolAddress((void**)&qlin, g_qlin);
    cudaGetSymbolAddress((void**)&klin, g_klin);
    cudaGetSymbolAddress((void**)&vlin, g_vlin);
    cudaGetSymbolAddress((void**)&o, g_o);

    dim3 t256(256);
    // Q projection: 1024x4096 @ 4096
    gemm_tf32<<<dim3(DMODEL / GBN, QLEN / GBM, 1), t256>>>(
        hidden, Wq, qlin, Wq, qlin, DMODEL, DMODEL);
    // K and V projections fused via blockIdx.z: 1024x1024 @ 4096 each
    gemm_tf32<<<dim3((NKV * HD) / GBN, QLEN / GBM, 2), t256>>>(
        hidden, Wk, klin, Wv, vlin, NKV * HD, DMODEL);
    rope_kernel<<<dim3(QLEN, NH + 2 * NKV), 128>>>();
    gqk_kernel<<<dim3(QLEN, NH), 32>>>(sorted_channel);
    attn_kernel<<<dim3(QLEN, NH), 256>>>();
    // output projection: 1024x4096 @ 4096
    gemm_tf32<<<dim3(DMODEL / GBN, QLEN / GBM, 1), t256>>>(
        o, Wo, out, Wo, out, DMODEL, DMODEL);
}